// round 1
// baseline (speedup 1.0000x reference)
#include <cuda_runtime.h>
#include <math.h>

#define HH 512
#define WW 512
#define BB 16
#define IMG (HH*WW)            // 262144 = 1<<18
#define TOT (BB*IMG)           // 4194304

// Scratch (static __device__ arrays: allocation-free)
__device__ float g_m  [TOT];   // marker1 -> becomes xh
__device__ float g_m2 [TOT];   // marker2 -> rec2
__device__ float g_rmx[TOT];   // Rmax
__device__ float g_m3 [TOT];   // marker3 -> R
__device__ int   g_flags[2];   // [0]: any Rmax==0, [1]: any Rmax==1
__device__ float g_cc[BB];

// ---------------------------------------------------------------------------
// Tiled chaotic-relaxation reconstruction step.
// Tile 32x32 (+1 halo) in smem, block 32x8, 4 rows per thread.
// Iterates to tile-local fixpoint (early exit), writes back only if changed.
// Monotone => in-place global updates with stale halos are safe.
// ---------------------------------------------------------------------------
__global__ void __launch_bounds__(256) recon_kernel(float* __restrict__ marker,
                                                    const float* __restrict__ mask)
{
    __shared__ float sm[34][34];
    const int img = blockIdx.z;
    const int x0 = blockIdx.x * 32;
    const int y0 = blockIdx.y * 32;
    float* mk = marker + (size_t)img * IMG;
    const float* msk = mask + (size_t)img * IMG;
    const int tid = threadIdx.y * 32 + threadIdx.x;

    // Load 34x34 region (halo = -inf outside image)
    for (int i = tid; i < 34 * 34; i += 256) {
        int ly = i / 34, lx = i - ly * 34;
        int gy = y0 + ly - 1, gx = x0 + lx - 1;
        float v = -INFINITY;
        if (gx >= 0 && gx < WW && gy >= 0 && gy < HH) v = mk[gy * WW + gx];
        sm[ly][lx] = v;
    }

    float mval[4], cur[4];
#pragma unroll
    for (int k = 0; k < 4; k++) {
        int y = y0 + threadIdx.y + 8 * k;
        mval[k] = msk[y * WW + x0 + threadIdx.x];
    }
    __syncthreads();
#pragma unroll
    for (int k = 0; k < 4; k++)
        cur[k] = sm[threadIdx.y + 8 * k + 1][threadIdx.x + 1];

    bool any = false;
    for (int it = 0; it < 72; ++it) {
        float nv[4];
        bool ch = false;
#pragma unroll
        for (int k = 0; k < 4; k++) {
            int ly = threadIdx.y + 8 * k + 1;
            int lx = threadIdx.x + 1;
            float a = fmaxf(fmaxf(sm[ly-1][lx-1], sm[ly-1][lx]), sm[ly-1][lx+1]);
            float b = fmaxf(fmaxf(sm[ly  ][lx-1], cur[k]      ), sm[ly  ][lx+1]);
            float c = fmaxf(fmaxf(sm[ly+1][lx-1], sm[ly+1][lx]), sm[ly+1][lx+1]);
            nv[k] = fminf(fmaxf(fmaxf(a, b), c), mval[k]);
            if (nv[k] > cur[k]) ch = true;
        }
        __syncthreads();
#pragma unroll
        for (int k = 0; k < 4; k++) {
            if (nv[k] > cur[k]) {
                sm[threadIdx.y + 8 * k + 1][threadIdx.x + 1] = nv[k];
                cur[k] = nv[k];
            }
        }
        any |= ch;
        if (!__syncthreads_or(ch)) break;
    }

    if (__syncthreads_or(any)) {
#pragma unroll
        for (int k = 0; k < 4; k++) {
            int y = y0 + threadIdx.y + 8 * k;
            mk[y * WW + x0 + threadIdx.x] = cur[k];
        }
    }
}

// ---------------------------------------------------------------------------
// Pointwise / reduction helpers
// ---------------------------------------------------------------------------
__global__ void k_init()
{
    if (threadIdx.x < 2)  g_flags[threadIdx.x] = 0;
    if (threadIdx.x < BB) g_cc[threadIdx.x] = 0.0f;
}

__global__ void k_sub_h(const float* __restrict__ x, const float* __restrict__ h)
{
    int i = blockIdx.x * 256 + threadIdx.x;
    g_m[i] = x[i] - h[i >> 18];
}

__global__ void k_sub_eps()
{
    int i = blockIdx.x * 256 + threadIdx.x;
    g_m2[i] = g_m[i] - 1e-5f;
}

__global__ void k_rmax_m3(const float* __restrict__ u)
{
    int i = blockIdx.x * 256 + threadIdx.x;
    float r = (g_m[i] - g_m2[i] > 0.0f) ? 1.0f : 0.0f;
    g_rmx[i] = r;
    g_m3[i]  = fminf(u[i], r);
    if (r == 0.0f) g_flags[0] = 1;   // benign races: all write 1
    else           g_flags[1] = 1;
}

__global__ void k_detect(const float* __restrict__ u)
{
    __shared__ float red[256];
    const int img = blockIdx.y;
    int base = (img << 18) + blockIdx.x * 1024 + threadIdx.x;
    float s = 0.0f;
#pragma unroll
    for (int k = 0; k < 4; k++) {
        int i = base + (k << 8);
        s += (u[i] == g_m3[i]) ? 1.0f : 0.0f;
    }
    red[threadIdx.x] = s;
    __syncthreads();
    for (int off = 128; off > 0; off >>= 1) {
        if (threadIdx.x < off) red[threadIdx.x] += red[threadIdx.x + off];
        __syncthreads();
    }
    if (threadIdx.x == 0) atomicAdd(&g_cc[img], red[0]);
}

__global__ void k_final(float* __restrict__ out)
{
    int i = threadIdx.x;
    if (i < BB) {
        float maxR = g_flags[1] ? 1.0f : 0.0f;
        float minR = g_flags[0] ? 0.0f : 1.0f;
        float diff = maxR - minR;
        float cc = g_cc[i];
        out[i] = fminf(cc, 100.0f * diff * cc);
    }
}

__global__ void k_copy_xh(float* __restrict__ out)
{
    int i = blockIdx.x * 256 + threadIdx.x;
    out[16 + i] = g_m[i];
}

// ---------------------------------------------------------------------------
extern "C" void kernel_launch(void* const* d_in, const int* in_sizes, int n_in,
                              void* d_out, int out_size)
{
    // Identify inputs by size (x and u are 4194304, h is 16; x precedes u)
    const float *x = nullptr, *h = nullptr, *u = nullptr;
    for (int i = 0; i < n_in; i++) {
        if (in_sizes[i] == BB) h = (const float*)d_in[i];
        else if (!x)           x = (const float*)d_in[i];
        else                   u = (const float*)d_in[i];
    }
    float* out = (float*)d_out;

    float *pm, *pm2, *prmx, *pm3;
    cudaGetSymbolAddress((void**)&pm,   g_m);
    cudaGetSymbolAddress((void**)&pm2,  g_m2);
    cudaGetSymbolAddress((void**)&prmx, g_rmx);
    cudaGetSymbolAddress((void**)&pm3,  g_m3);

    const dim3 rgrid(WW / 32, HH / 32, BB);   // 16 x 16 x 16
    const dim3 rblk(32, 8);
    const int NPW = TOT / 256;                // 16384 blocks for pointwise

    k_init<<<1, 32>>>();

    // Reconstruction 1: xh = rec(x - h, x)
    k_sub_h<<<NPW, 256>>>(x, h);
    for (int i = 0; i < 28; i++) recon_kernel<<<rgrid, rblk>>>(pm, x);

    // Reconstruction 2: rec(xh - eps, xh)
    k_sub_eps<<<NPW, 256>>>();
    for (int i = 0; i < 28; i++) recon_kernel<<<rgrid, rblk>>>(pm2, pm);

    // Rmax, M, flags
    k_rmax_m3<<<NPW, 256>>>(u);

    // Reconstruction 3: R = rec(min(u,Rmax), Rmax)
    for (int i = 0; i < 16; i++) recon_kernel<<<rgrid, rblk>>>(pm3, prmx);

    // CC and outputs
    k_detect<<<dim3(IMG / 1024, BB), 256>>>(u);
    k_final<<<1, 32>>>(out);
    k_copy_xh<<<NPW, 256>>>(out);
}

// round 2
// speedup vs baseline: 2.1457x; 2.1457x over previous
#include <cuda_runtime.h>
#include <math.h>

#define HH 512
#define WW 512
#define BB 16
#define IMG (HH*WW)            // 262144 = 1<<18
#define TOT (BB*IMG)           // 4194304
#define NTILES 4096            // 16 x-tiles * 16 y-tiles * 16 images
#define MAXR1 28
#define MAXR2 28
#define MAXR3 16
#define NFLAGS (MAXR1+MAXR2+MAXR3)

// Scratch (static __device__ arrays: allocation-free)
__device__ float g_m  [TOT];
__device__ float g_m2 [TOT];
__device__ float g_rmx[TOT];
__device__ float g_m3 [TOT];
__device__ unsigned char g_dirty[2][NTILES];
__device__ int   g_chflag[NFLAGS];
__device__ int   g_rflags[2];          // [0]: any Rmax==0, [1]: any Rmax==1
__device__ float g_cc[BB];
__device__ unsigned g_arrive  = 0;
__device__ unsigned g_release = 0;

// ---------------------------------------------------------------------------
// Software grid barrier (all blocks co-resident by construction).
// ---------------------------------------------------------------------------
__device__ __forceinline__ void gbar(unsigned nb, unsigned& target)
{
    __syncthreads();
    if (threadIdx.x == 0) {
        __threadfence();
        unsigned old = atomicInc(&g_arrive, nb - 1);
        if (old == nb - 1) {
            atomicAdd(&g_release, 1);
        } else {
            while (*((volatile unsigned*)&g_release) < target) __nanosleep(40);
        }
        __threadfence();
    }
    target++;
    __syncthreads();
}

// ---------------------------------------------------------------------------
// One 32x32 tile: local chaotic relaxation to fixpoint in shared memory.
// All global marker traffic via __ldcg/__stcg (cross-SM coherence).
// Returns block-uniform "tile changed".
// ---------------------------------------------------------------------------
__device__ __forceinline__ bool process_tile(
    float* __restrict__ mk, const float* __restrict__ msk,
    int img, int x0, int y0, float (*sm)[34], int tid)
{
    float* m        = mk  + (size_t)img * IMG;
    const float* ms = msk + (size_t)img * IMG;
    const int ty = tid >> 5, tx = tid & 31;

    for (int i = tid; i < 34 * 34; i += 256) {
        int ly = i / 34, lx = i - ly * 34;
        int gy = y0 + ly - 1, gx = x0 + lx - 1;
        float v = -INFINITY;
        if ((unsigned)gx < WW && (unsigned)gy < HH) v = __ldcg(&m[gy * WW + gx]);
        sm[ly][lx] = v;
    }
    float mval[4], cur[4];
#pragma unroll
    for (int k = 0; k < 4; k++)
        mval[k] = __ldcg(&ms[(y0 + ty + 8 * k) * WW + x0 + tx]);
    __syncthreads();
#pragma unroll
    for (int k = 0; k < 4; k++)
        cur[k] = sm[ty + 8 * k + 1][tx + 1];

    bool any = false;
    for (int it = 0; it < 64; ++it) {
        float nv[4];
        bool ch = false;
#pragma unroll
        for (int k = 0; k < 4; k++) {
            int ly = ty + 8 * k + 1, lx = tx + 1;
            float a = fmaxf(fmaxf(sm[ly-1][lx-1], sm[ly-1][lx]), sm[ly-1][lx+1]);
            float b = fmaxf(fmaxf(sm[ly  ][lx-1], cur[k]      ), sm[ly  ][lx+1]);
            float c = fmaxf(fmaxf(sm[ly+1][lx-1], sm[ly+1][lx]), sm[ly+1][lx+1]);
            nv[k] = fminf(fmaxf(fmaxf(a, b), c), mval[k]);
            if (nv[k] > cur[k]) ch = true;
        }
        __syncthreads();
#pragma unroll
        for (int k = 0; k < 4; k++) {
            if (nv[k] > cur[k]) {
                sm[ty + 8 * k + 1][tx + 1] = nv[k];
                cur[k] = nv[k];
            }
        }
        any |= ch;
        if (!__syncthreads_or(ch)) break;
    }

    bool blkany = __syncthreads_or(any);
    if (blkany) {
#pragma unroll
        for (int k = 0; k < 4; k++)
            __stcg(&m[(y0 + ty + 8 * k) * WW + x0 + tx], cur[k]);
    }
    return blkany;
}

// ---------------------------------------------------------------------------
// Reconstruction: rounds of tile relaxation with dirty-skip + exact early exit.
// ---------------------------------------------------------------------------
__device__ __forceinline__ void recon(
    float* mk, const float* msk, int maxr, int flagbase,
    unsigned nb, unsigned& target, float (*sm)[34], int tid, int bid)
{
    for (int r = 0; r < maxr; ++r) {
        const int par = r & 1;
        for (int t = bid; t < NTILES; t += (int)nb) {
            bool need = true;
            if (r > 0) {
                bool mine = false;
                if (tid < 9) {
                    int dy = tid / 3 - 1, dx = tid % 3 - 1;
                    int tyy = (t >> 4) & 15, txx = t & 15;
                    int ny = tyy + dy, nx = txx + dx;
                    if ((unsigned)ny < 16u && (unsigned)nx < 16u)
                        mine = (*(volatile unsigned char*)&g_dirty[par ^ 1][t + dy * 16 + dx]) != 0;
                }
                need = __syncthreads_or(mine);
            }
            bool ch = false;
            if (need) {
                int img = t >> 8, local = t & 255;
                ch = process_tile(mk, msk, img, (local & 15) * 32, (local >> 4) * 32, sm, tid);
            }
            if (tid == 0) {
                *(volatile unsigned char*)&g_dirty[par][t] = ch ? 1 : 0;
                if (ch) *(volatile int*)&g_chflag[flagbase + r] = 1;
            }
            __syncthreads();
        }
        gbar(nb, target);
        if (*(volatile int*)&g_chflag[flagbase + r] == 0) break;  // block-uniform
    }
}

// ---------------------------------------------------------------------------
// The whole pipeline in one persistent kernel.
// ---------------------------------------------------------------------------
__global__ void __launch_bounds__(256) persistent_kernel(
    const float* __restrict__ x, const float* __restrict__ h,
    const float* __restrict__ u, float* __restrict__ out, int nbi)
{
    __shared__ float sm[34][34];
    __shared__ float red[8];
    const unsigned nb = (unsigned)nbi;
    const int tid = threadIdx.x;
    const int bid = blockIdx.x;
    const int gid = bid * 256 + tid;
    const int nthr = nbi * 256;
    unsigned target = *((volatile unsigned*)&g_release) + 1;

    // ---- P0: g_m = x - h ; reset flags/counters --------------------------
    {
        const float4* x4 = (const float4*)x;
        float4* m4 = (float4*)g_m;
        for (int i4 = gid; i4 < TOT / 4; i4 += nthr) {
            float4 v = __ldg(&x4[i4]);
            float hh = __ldg(&h[i4 >> 16]);
            v.x -= hh; v.y -= hh; v.z -= hh; v.w -= hh;
            __stcg(&m4[i4], v);
        }
        if (bid == 0) {
            if (tid < NFLAGS) __stcg(&g_chflag[tid], 0);
            if (tid < 2)      __stcg(&g_rflags[tid], 0);
            if (tid < BB)     __stcg(&g_cc[tid], 0.0f);
        }
    }
    gbar(nb, target);

    // ---- Rec1: xh = rec(x - h, x) ----------------------------------------
    recon(g_m, x, MAXR1, 0, nb, target, sm, tid, bid);

    // ---- P1: out[16..] = xh ; g_m2 = xh - eps ----------------------------
    {
        const float4* m4 = (const float4*)g_m;
        float4* m24 = (float4*)g_m2;
        float4* o4 = (float4*)(out + 16);
        for (int i4 = gid; i4 < TOT / 4; i4 += nthr) {
            float4 v = __ldcg(&m4[i4]);
            o4[i4] = v;
            v.x -= 1e-5f; v.y -= 1e-5f; v.z -= 1e-5f; v.w -= 1e-5f;
            __stcg(&m24[i4], v);
        }
    }
    gbar(nb, target);

    // ---- Rec2: rec(xh - eps, xh) -----------------------------------------
    recon(g_m2, g_m, MAXR2, MAXR1, nb, target, sm, tid, bid);

    // ---- P2: Rmax = (xh > rec2); M = min(u, Rmax); global min/max flags --
    {
        const float4* m4  = (const float4*)g_m;
        const float4* m24 = (const float4*)g_m2;
        const float4* u4  = (const float4*)u;
        float4* r4 = (float4*)g_rmx;
        float4* m34 = (float4*)g_m3;
        bool a0 = false, a1 = false;
        for (int i4 = gid; i4 < TOT / 4; i4 += nthr) {
            float4 a = __ldcg(&m4[i4]);
            float4 b = __ldcg(&m24[i4]);
            float4 uu = __ldg(&u4[i4]);
            float4 r, m3;
            r.x = (a.x > b.x) ? 1.0f : 0.0f;
            r.y = (a.y > b.y) ? 1.0f : 0.0f;
            r.z = (a.z > b.z) ? 1.0f : 0.0f;
            r.w = (a.w > b.w) ? 1.0f : 0.0f;
            if (r.x == 0.f || r.y == 0.f || r.z == 0.f || r.w == 0.f) a0 = true;
            if (r.x == 1.f || r.y == 1.f || r.z == 1.f || r.w == 1.f) a1 = true;
            m3.x = fminf(uu.x, r.x); m3.y = fminf(uu.y, r.y);
            m3.z = fminf(uu.z, r.z); m3.w = fminf(uu.w, r.w);
            __stcg(&r4[i4], r);
            __stcg(&m34[i4], m3);
        }
        bool b0 = __syncthreads_or(a0);
        bool b1 = __syncthreads_or(a1);
        if (tid == 0) {
            if (b0) *(volatile int*)&g_rflags[0] = 1;
            if (b1) *(volatile int*)&g_rflags[1] = 1;
        }
    }
    gbar(nb, target);

    // ---- Rec3: R = rec(M, Rmax) ------------------------------------------
    recon(g_m3, g_rmx, MAXR3, MAXR1 + MAXR2, nb, target, sm, tid, bid);

    // ---- P3: CC[img] = sum(u == R) ---------------------------------------
    {
        const int ty = tid >> 5, tx = tid & 31;
        for (int t = bid; t < NTILES; t += nbi) {
            int img = t >> 8, local = t & 255;
            int x0 = (local & 15) * 32, y0 = (local >> 4) * 32;
            const float* uu = u + (size_t)img * IMG;
            const float* m3 = g_m3 + (size_t)img * IMG;
            float s = 0.0f;
#pragma unroll
            for (int k = 0; k < 4; k++) {
                int idx = (y0 + ty + 8 * k) * WW + x0 + tx;
                s += (__ldg(&uu[idx]) == __ldcg(&m3[idx])) ? 1.0f : 0.0f;
            }
#pragma unroll
            for (int off = 16; off; off >>= 1)
                s += __shfl_down_sync(0xffffffffu, s, off);
            if ((tid & 31) == 0) red[tid >> 5] = s;
            __syncthreads();
            if (tid == 0) {
                float tot = 0.0f;
#pragma unroll
                for (int w = 0; w < 8; w++) tot += red[w];
                atomicAdd(&g_cc[img], tot);
            }
            __syncthreads();
        }
    }
    gbar(nb, target);

    // ---- P4: CC_ ---------------------------------------------------------
    if (bid == 0 && tid < BB) {
        float maxR = (*(volatile int*)&g_rflags[1]) ? 1.0f : 0.0f;
        float minR = (*(volatile int*)&g_rflags[0]) ? 0.0f : 1.0f;
        float diff = maxR - minR;
        float cc = *(volatile float*)&g_cc[tid];
        out[tid] = fminf(cc, 100.0f * diff * cc);
    }
}

// ---------------------------------------------------------------------------
extern "C" void kernel_launch(void* const* d_in, const int* in_sizes, int n_in,
                              void* d_out, int out_size)
{
    // Identify inputs by size (x and u are 4194304, h is 16; x precedes u)
    const float *x = nullptr, *h = nullptr, *u = nullptr;
    for (int i = 0; i < n_in; i++) {
        if (in_sizes[i] == BB) h = (const float*)d_in[i];
        else if (!x)           x = (const float*)d_in[i];
        else                   u = (const float*)d_in[i];
    }
    float* out = (float*)d_out;

    int dev = 0, sms = 0, occ = 0;
    cudaGetDevice(&dev);
    cudaDeviceGetAttribute(&sms, cudaDevAttrMultiProcessorCount, dev);
    cudaOccupancyMaxActiveBlocksPerMultiprocessor(&occ, persistent_kernel, 256, 0);
    int nb = sms * occ;
    if (nb <= 0) nb = 256;       // conservative fallback, guaranteed resident
    if (nb > 2048) nb = 2048;

    persistent_kernel<<<nb, 256>>>(x, h, u, out, nb);
}